// round 2
// baseline (speedup 1.0000x reference)
#include <cuda_runtime.h>

// DotAttentionEluX: the reference's row-normalized rank-1 attention collapses:
//   attn[i,j] = ks[j] / sum_j ks[j]   (qs[i] and the 1/sqrt(D) scale cancel)
//   out[b,h,i,:] = (sum_j ks[j] * V[b,h,j,:]) / (sum_j ks[j])   for ALL i.
// So: never read Q; compute one 64-vector per (b,h); broadcast it to 2048 rows.

#define L_SEQ 2048
#define D_DIM 64
#define BH    32              // B*H = 4*8
#define NCHUNK 64
#define ROWS_PER_CHUNK 32     // L_SEQ / NCHUNK
#define ROWBLKS 16
#define ROWS_PER_BLOCK 128    // L_SEQ / ROWBLKS

// Scratch (no device allocation allowed): per-(bh,chunk) partial sums.
__device__ float g_part [BH * NCHUNK * D_DIM];   // 512 KB
__device__ float g_partS[BH * NCHUNK];

__global__ __launch_bounds__(256, 8)
void phase1_accum(const float* __restrict__ Kp, const float* __restrict__ Vp) {
    const int chunk = blockIdx.x;
    const int bh    = blockIdx.y;
    const int tid   = threadIdx.x;
    const int w     = tid >> 5;     // warp 0..7
    const int l     = tid & 31;     // lane

    const size_t base = ((size_t)bh * L_SEQ + (size_t)chunk * ROWS_PER_CHUNK) * D_DIM;
    const float* kbase = Kp + base;
    const float* vbase = Vp + base;

    // Each warp handles 4 rows; lane l owns dims {2l, 2l+1}.
    float accx = 0.f, accy = 0.f;
    float ssum = 0.f;
    #pragma unroll
    for (int r = 0; r < 4; r++) {
        const int row = w * 4 + r;
        const float2 kv = *(const float2*)(kbase + row * D_DIM + 2 * l);
        const float f0 = kv.x > 0.f ? kv.x + 1.f : __expf(kv.x);
        const float f1 = kv.y > 0.f ? kv.y + 1.f : __expf(kv.y);
        float ks = f0 + f1;
        #pragma unroll
        for (int o = 16; o > 0; o >>= 1)
            ks += __shfl_xor_sync(0xffffffffu, ks, o);   // all lanes: row feature-sum
        const float2 vv = *(const float2*)(vbase + row * D_DIM + 2 * l);
        accx += ks * vv.x;
        accy += ks * vv.y;
        ssum += ks;
    }

    __shared__ float sacc[8][D_DIM];
    __shared__ float sS[8];
    sacc[w][2 * l]     = accx;
    sacc[w][2 * l + 1] = accy;
    if (l == 0) sS[w] = ssum;
    __syncthreads();

    if (tid < D_DIM) {
        float s = 0.f;
        #pragma unroll
        for (int i = 0; i < 8; i++) s += sacc[i][tid];
        g_part[((size_t)bh * NCHUNK + chunk) * D_DIM + tid] = s;
    } else if (tid == D_DIM) {
        float s = 0.f;
        #pragma unroll
        for (int i = 0; i < 8; i++) s += sS[i];
        g_partS[bh * NCHUNK + chunk] = s;
    }
}

__global__ __launch_bounds__(256, 8)
void phase2_broadcast(float* __restrict__ out) {
    const int rb  = blockIdx.x;   // row block 0..15
    const int bh  = blockIdx.y;
    const int tid = threadIdx.x;

    __shared__ float srow[D_DIM];
    __shared__ float sS;

    if (tid < D_DIM) {
        float s = 0.f;
        const float* p = g_part + (size_t)bh * NCHUNK * D_DIM + tid;
        #pragma unroll 8
        for (int c = 0; c < NCHUNK; c++) s += p[c * D_DIM];   // L2 hits
        srow[tid] = s;
    } else if (tid == D_DIM) {
        float s = 0.f;
        const float* p = g_partS + bh * NCHUNK;
        #pragma unroll 8
        for (int c = 0; c < NCHUNK; c++) s += p[c];
        sS = s;
    }
    __syncthreads();
    if (tid < D_DIM) srow[tid] *= (1.0f / sS);
    __syncthreads();

    // Broadcast the single normalized row to 128 output rows, float4 stores.
    const float4* s4  = (const float4*)srow;               // 16 float4 per row
    float4*       o4  = (float4*)(out + ((size_t)bh * L_SEQ + (size_t)rb * ROWS_PER_BLOCK) * D_DIM);
    const float4  myv = s4[tid & 15];                      // i%16 == tid%16 (stride 256 ≡ 0 mod 16)
    #pragma unroll
    for (int i = tid; i < ROWS_PER_BLOCK * 16; i += 256)
        o4[i] = myv;
}

extern "C" void kernel_launch(void* const* d_in, const int* in_sizes, int n_in,
                              void* d_out, int out_size) {
    // metadata order: query (UNUSED), key, value
    const float* Kp = (const float*)d_in[1];
    const float* Vp = (const float*)d_in[2];
    float* out = (float*)d_out;

    phase1_accum<<<dim3(NCHUNK, BH), 256>>>(Kp, Vp);
    phase2_broadcast<<<dim3(ROWBLKS, BH), 256>>>(out);
}

// round 7
// speedup vs baseline: 1.0109x; 1.0109x over previous
#include <cuda_runtime.h>
#include <cstdint>

// DotAttentionEluX collapses: attn[i,j] = ks[j]/sum(ks), so
//   out[b,h,i,:] = (sum_j ks[j] V[b,h,j,:]) / sum_j ks[j]  for ALL i (Q unused).
// Phase1: partial ks-weighted V sums per 32-row chunk (LDG.128, near LTS cap).
// Phase2: reduce 64 chunks, replicate row in SMEM, cp.async.bulk stores
//         (4 bulk copies/block instead of 2048 STG.128 -> kills the STG issue floor).

#define L_SEQ 2048
#define D_DIM 64
#define BH    32
#define NCHUNK 64
#define ROWS_PER_CHUNK 32
#define P2_BLOCKS 8            // blocks per bh; each writes 256 rows = 64 KB
#define P2_ROWS   256

__device__ float g_part [BH * NCHUNK * D_DIM];
__device__ float g_partS[BH * NCHUNK];

__global__ __launch_bounds__(256, 8)
void phase1_accum(const float* __restrict__ Kp, const float* __restrict__ Vp) {
    const int chunk = blockIdx.x;
    const int bh    = blockIdx.y;
    const int tid   = threadIdx.x;
    const int w = tid >> 5, l = tid & 31;
    const int g = l >> 4, c = l & 15;          // 16 lanes per row, float4 column c

    const size_t base = ((size_t)bh * L_SEQ + (size_t)chunk * ROWS_PER_CHUNK) * D_DIM;
    const float4* K4 = (const float4*)(Kp + base);
    const float4* V4 = (const float4*)(Vp + base);

    float4 acc = make_float4(0.f, 0.f, 0.f, 0.f);
    float ssum = 0.f;
    #pragma unroll
    for (int s = 0; s < 2; s++) {
        const int row = w * 4 + s * 2 + g;     // 2 rows per warp per step
        const float4 k4 = K4[row * 16 + c];
        const float f0 = k4.x > 0.f ? k4.x + 1.f : __expf(k4.x);
        const float f1 = k4.y > 0.f ? k4.y + 1.f : __expf(k4.y);
        const float f2 = k4.z > 0.f ? k4.z + 1.f : __expf(k4.z);
        const float f3 = k4.w > 0.f ? k4.w + 1.f : __expf(k4.w);
        float ks = (f0 + f1) + (f2 + f3);
        #pragma unroll
        for (int o = 8; o > 0; o >>= 1)
            ks += __shfl_xor_sync(0xffffffffu, ks, o);   // 16-lane row sum
        const float4 v4 = V4[row * 16 + c];
        acc.x += ks * v4.x; acc.y += ks * v4.y;
        acc.z += ks * v4.z; acc.w += ks * v4.w;
        if (c == 0) ssum += ks;
    }

    __shared__ float4 sacc[16][16];   // [w*2+g][c]
    __shared__ float  sS[16];
    sacc[w * 2 + g][c] = acc;
    if (c == 0) sS[w * 2 + g] = ssum;
    __syncthreads();

    if (tid < 16) {
        float4 s = make_float4(0.f, 0.f, 0.f, 0.f);
        #pragma unroll
        for (int i = 0; i < 16; i++) {
            const float4 a = sacc[i][tid];
            s.x += a.x; s.y += a.y; s.z += a.z; s.w += a.w;
        }
        ((float4*)(g_part + ((size_t)bh * NCHUNK + chunk) * D_DIM))[tid] = s;
    } else if (tid == 16) {
        float s = 0.f;
        #pragma unroll
        for (int i = 0; i < 16; i++) s += sS[i];
        g_partS[bh * NCHUNK + chunk] = s;
    }
}

__global__ __launch_bounds__(256, 4)
void phase2_broadcast(float* __restrict__ out) {
    const int rb  = blockIdx.x;    // 0..P2_BLOCKS-1
    const int bh  = blockIdx.y;
    const int tid = threadIdx.x;

    __shared__ float srow[D_DIM];
    __shared__ float sS;
    __shared__ __align__(16) float sbuf[64 * D_DIM];   // 64 row replicas = 16 KB

    if (tid < D_DIM) {
        float s = 0.f;
        const float* p = g_part + (size_t)bh * NCHUNK * D_DIM + tid;
        #pragma unroll 16
        for (int cc = 0; cc < NCHUNK; cc++) s += p[cc * D_DIM];   // L2 hits
        srow[tid] = s;
    } else if (tid == D_DIM) {
        float s = 0.f;
        const float* p = g_partS + bh * NCHUNK;
        #pragma unroll 16
        for (int i = 0; i < NCHUNK; i++) s += p[i];
        sS = s;
    }
    __syncthreads();

    const float inv = 1.0f / sS;
    const float* r = srow + 4 * (tid & 15);
    const float4 myv = make_float4(r[0] * inv, r[1] * inv, r[2] * inv, r[3] * inv);

    float4* b4 = (float4*)sbuf;                 // 1024 float4; index%16 == float4 col
    #pragma unroll
    for (int i = 0; i < 4; i++) b4[tid + i * 256] = myv;
    __syncthreads();
    asm volatile("fence.proxy.async.shared::cta;" ::: "memory");

    if (tid == 0) {
        uint32_t src;
        asm("{ .reg .u64 t; cvta.to.shared.u64 t, %1; cvt.u32.u64 %0, t; }"
            : "=r"(src) : "l"(sbuf));
        char* dst = (char*)out
                  + (((size_t)bh * L_SEQ + (size_t)rb * P2_ROWS) * D_DIM) * sizeof(float);
        #pragma unroll
        for (int i = 0; i < 4; i++) {
            asm volatile(
                "cp.async.bulk.global.shared::cta.bulk_group [%0], [%1], %2;"
                :: "l"(dst + (size_t)i * 16384), "r"(src), "r"(16384) : "memory");
        }
        asm volatile("cp.async.bulk.commit_group;" ::: "memory");
        asm volatile("cp.async.bulk.wait_group 0;" ::: "memory");
    }
}

extern "C" void kernel_launch(void* const* d_in, const int* in_sizes, int n_in,
                              void* d_out, int out_size) {
    const float* Kp = (const float*)d_in[1];   // query (d_in[0]) is provably unused
    const float* Vp = (const float*)d_in[2];
    float* out = (float*)d_out;

    phase1_accum<<<dim3(NCHUNK, BH), 256>>>(Kp, Vp);
    phase2_broadcast<<<dim3(P2_BLOCKS, BH), 256>>>(out);
}